// round 1
// baseline (speedup 1.0000x reference)
#include <cuda_runtime.h>

// Problem constants
#define B_ 8
#define C_ 256
#define N_ 16384
#define K_ 128

// Tiling
#define TN 128              // points per chunk
#define TC 64               // channels per tile block
#define SPLITS 19           // CTAs per batch -> 8*19 = 152 CTAs = #SMs on GB300
#define TPB 1024
#define TAB_ELEMS (K_ * C_) // 32768 table entries per CTA

// Per-CTA partial tables (ordered-uint keys). 8*19*32768*4 = ~19.9 MB.
__device__ unsigned int g_scratch[B_ * SPLITS * TAB_ELEMS];

// Monotone float -> uint key: unsigned order == float order.
__device__ __forceinline__ unsigned int fkey(float f) {
    int i = __float_as_int(f);
    return (i >= 0) ? ((unsigned int)i | 0x80000000u) : ~(unsigned int)i;
}
__device__ __forceinline__ float funkey(unsigned int k) {
    unsigned int i = (k & 0x80000000u) ? (k & 0x7FFFFFFFu) : ~k;
    return __int_as_float((int)i);
}

// Phase 1: fused transpose (b,c,n)->(b,n,c) + per-CTA segment-max table.
__global__ __launch_bounds__(TPB, 1)
void seg_phase1(const float* __restrict__ pf, const int* __restrict__ cids,
                float* __restrict__ out_pf) {
    extern __shared__ unsigned int smem[];
    unsigned int* tab = smem;                          // K_*C_ keys (128 KB)
    float* tile = (float*)(smem + TAB_ELEMS);          // [TC][TN+1] padded tile
    int* scid = (int*)(tile + TC * (TN + 1));          // TN cluster ids

    const int tid = threadIdx.x;
    const int b = blockIdx.y;
    const int s = blockIdx.x;

    // init table to "empty" sentinel (0 < key of every finite float)
    for (int i = tid; i < TAB_ELEMS; i += TPB) tab[i] = 0u;

    const float* src = pf + (size_t)b * C_ * N_;
    const int nchunks = N_ / TN;                       // 128

    for (int m = s; m < nchunks; m += SPLITS) {
        const int n0 = m * TN;
        __syncthreads();                               // prev chunk fully consumed
        if (tid < TN) scid[tid] = cids[b * N_ + n0 + tid];

        for (int cb = 0; cb < C_; cb += TC) {
            __syncthreads();                           // tile free, scid ready
            // load tile: coalesced along n
            #pragma unroll
            for (int k = 0; k < (TC * TN) / TPB; k++) {
                int i = tid + k * TPB;
                int cc = i >> 7;                       // i / TN
                int nn = i & (TN - 1);
                tile[cc * (TN + 1) + nn] = src[(size_t)(cb + cc) * N_ + n0 + nn];
            }
            __syncthreads();
            // write transposed (coalesced along c) + shared-atomic segment max
            const int c = tid & (TC - 1);
            #pragma unroll
            for (int p = tid >> 6; p < TN; p += TPB / TC) {
                float v = tile[c * (TN + 1) + p];      // conflict-free: stride 129
                out_pf[((size_t)b * N_ + n0 + p) * C_ + cb + c] = v;
                int cid = scid[p];
                if (cid >= 0)                          // -1 = dump segment, skip
                    atomicMax(&tab[cid * C_ + cb + c], fkey(v));
            }
        }
    }
    __syncthreads();

    // dump private table to scratch (coalesced)
    unsigned int* dst = g_scratch + ((size_t)b * SPLITS + s) * TAB_ELEMS;
    for (int i = tid; i < TAB_ELEMS; i += TPB) dst[i] = tab[i];
}

// Phase 2: reduce SPLITS partials per output, sentinel -> 0.0 (matches isfinite->0).
__global__ void seg_phase2(float* __restrict__ out_seg) {
    int i = blockIdx.x * blockDim.x + threadIdx.x;
    if (i >= B_ * TAB_ELEMS) return;
    int b = i / TAB_ELEMS;
    int j = i - b * TAB_ELEMS;
    const unsigned int* p = g_scratch + (size_t)b * SPLITS * TAB_ELEMS + j;
    unsigned int mx = 0u;
    #pragma unroll
    for (int s = 0; s < SPLITS; s++) mx = max(mx, p[(size_t)s * TAB_ELEMS]);
    out_seg[i] = (mx == 0u) ? 0.0f : funkey(mx);
}

extern "C" void kernel_launch(void* const* d_in, const int* in_sizes, int n_in,
                              void* d_out, int out_size) {
    const float* pf  = (const float*)d_in[0];   // point_features (B,C,N) f32
    const int*  cid  = (const int*)d_in[1];     // cluster_ids (B,N) i32
    float* out       = (float*)d_out;
    float* out_seg   = out;                     // (B*K, C)
    float* out_pf    = out + (size_t)B_ * K_ * C_; // (B*N, C)

    const size_t smem_bytes = (size_t)TAB_ELEMS * 4 + (size_t)TC * (TN + 1) * 4 + (size_t)TN * 4;
    cudaFuncSetAttribute(seg_phase1, cudaFuncAttributeMaxDynamicSharedMemorySize,
                         (int)smem_bytes);

    dim3 grid(SPLITS, B_);
    seg_phase1<<<grid, TPB, smem_bytes>>>(pf, cid, out_pf);
    seg_phase2<<<(B_ * TAB_ELEMS + 255) / 256, 256>>>(out_seg);
}

// round 2
// speedup vs baseline: 1.2281x; 1.2281x over previous
#include <cuda_runtime.h>

// Problem constants
#define B_ 8
#define C_ 256
#define N_ 16384
#define K_ 128

// Tiling
#define TN 128                  // points per chunk
#define TC 64                   // channels per tile block
#define SPLITS 19               // 8*19 = 152 CTAs = #SMs
#define TPB 1024
#define TAB_ELEMS (K_ * C_)     // 32768 per-CTA table entries
#define NCHUNK (N_ / TN)        // 128
#define TSTRIDE (TN + 1)        // padded tile row stride (conflict-free-ish)

// Per-CTA partial tables (ordered-uint keys). ~19.9 MB.
__device__ unsigned int g_scratch[B_ * SPLITS * TAB_ELEMS];

// Monotone float -> uint key: unsigned order == float order.
__device__ __forceinline__ unsigned int fkey(float f) {
    int i = __float_as_int(f);
    return (i >= 0) ? ((unsigned int)i | 0x80000000u) : ~(unsigned int)i;
}
__device__ __forceinline__ float funkey(unsigned int k) {
    unsigned int i = (k & 0x80000000u) ? (k & 0x7FFFFFFFu) : ~k;
    return __int_as_float((int)i);
}

// Phase 1: fused transpose + per-CTA segment-max, software-pipelined.
__global__ __launch_bounds__(TPB, 1)
void seg_phase1(const float* __restrict__ pf, const int* __restrict__ cids,
                float* __restrict__ out_pf) {
    extern __shared__ unsigned int smem[];
    unsigned int* tab = smem;                          // 128 KB
    float* tile = (float*)(smem + TAB_ELEMS);          // [TC][TN+1]
    int* scid = (int*)(tile + TC * TSTRIDE);           // TN ids

    const int tid = threadIdx.x;
    const int b = blockIdx.y;
    const int s = blockIdx.x;

    for (int i = tid; i < TAB_ELEMS; i += TPB) tab[i] = 0u;   // empty sentinel

    const float* src = pf + (size_t)b * C_ * N_;

    // Loader mapping: each thread owns fixed col ln, rows lr + 8k (k=0..7)
    const int lr = tid >> 7;        // 0..7
    const int ln = tid & 127;
    // Consumer mapping: 4 consecutive channels per thread -> STG.128
    const int c4 = (tid & 15) * 4;
    const int pb = tid >> 4;        // 0..63

    int m = s, cb = 0;
    int cidreg = 0;
    if (tid < TN) cidreg = cids[b * N_ + m * TN + tid];

    float r[8];
    {   // prime the pipeline: block (m=s, cb=0)
        const float* p0 = src + (size_t)lr * N_ + m * TN + ln;
        #pragma unroll
        for (int k = 0; k < 8; k++) r[k] = __ldcs(p0 + (size_t)(8 * k) * N_);
    }

    bool have = true;
    while (have) {
        __syncthreads();                               // prev tile fully consumed
        #pragma unroll
        for (int k = 0; k < 8; k++)
            tile[(lr + 8 * k) * TSTRIDE + ln] = r[k];
        if (cb == 0 && tid < TN) scid[tid] = cidreg;
        __syncthreads();                               // tile + scid ready

        const int n0 = m * TN;
        const int curcb = cb;

        // advance + prefetch next block into registers (hides LDG latency)
        int nm = m, ncb = cb + TC;
        if (ncb == C_) { ncb = 0; nm = m + SPLITS; }
        have = (nm < NCHUNK);
        if (have) {
            const float* p0 = src + (size_t)(ncb + lr) * N_ + nm * TN + ln;
            #pragma unroll
            for (int k = 0; k < 8; k++) r[k] = __ldcs(p0 + (size_t)(8 * k) * N_);
            if (ncb == 0 && tid < TN) cidreg = cids[b * N_ + nm * TN + tid];
        }

        // consume: transposed STG.128 + filtered shared atomicMax
        #pragma unroll
        for (int q = 0; q < 2; q++) {
            const int p = pb + q * 64;
            float v0 = tile[(c4 + 0) * TSTRIDE + p];
            float v1 = tile[(c4 + 1) * TSTRIDE + p];
            float v2 = tile[(c4 + 2) * TSTRIDE + p];
            float v3 = tile[(c4 + 3) * TSTRIDE + p];
            float4 vv = make_float4(v0, v1, v2, v3);
            __stcs((float4*)(out_pf + ((size_t)b * N_ + n0 + p) * C_ + curcb + c4), vv);
            const int cid = scid[p];
            if (cid >= 0) {
                unsigned int* cell = &tab[cid * C_ + curcb + c4];
                unsigned int k0 = fkey(v0); if (cell[0] < k0) atomicMax(cell + 0, k0);
                unsigned int k1 = fkey(v1); if (cell[1] < k1) atomicMax(cell + 1, k1);
                unsigned int k2 = fkey(v2); if (cell[2] < k2) atomicMax(cell + 2, k2);
                unsigned int k3 = fkey(v3); if (cell[3] < k3) atomicMax(cell + 3, k3);
            }
        }
        m = nm; cb = ncb;
    }
    __syncthreads();

    unsigned int* dst = g_scratch + ((size_t)b * SPLITS + s) * TAB_ELEMS;
    for (int i = tid; i < TAB_ELEMS; i += TPB) dst[i] = tab[i];
}

// Phase 2: reduce SPLITS partials, uint4-wide, sentinel -> 0.0
__global__ void seg_phase2(float* __restrict__ out_seg) {
    const int J4 = TAB_ELEMS / 4;                       // 8192 uint4 per (b)
    int g = blockIdx.x * blockDim.x + threadIdx.x;
    if (g >= B_ * J4) return;
    int b = g / J4;
    int j4 = g - b * J4;
    const uint4* p = (const uint4*)g_scratch + (size_t)b * SPLITS * J4 + j4;
    uint4 mx = make_uint4(0u, 0u, 0u, 0u);
    #pragma unroll
    for (int s = 0; s < SPLITS; s++) {
        uint4 v = p[(size_t)s * J4];
        mx.x = max(mx.x, v.x); mx.y = max(mx.y, v.y);
        mx.z = max(mx.z, v.z); mx.w = max(mx.w, v.w);
    }
    float4 o;
    o.x = mx.x ? funkey(mx.x) : 0.0f;
    o.y = mx.y ? funkey(mx.y) : 0.0f;
    o.z = mx.z ? funkey(mx.z) : 0.0f;
    o.w = mx.w ? funkey(mx.w) : 0.0f;
    ((float4*)out_seg)[g] = o;
}

extern "C" void kernel_launch(void* const* d_in, const int* in_sizes, int n_in,
                              void* d_out, int out_size) {
    const float* pf = (const float*)d_in[0];     // (B,C,N) f32
    const int* cid  = (const int*)d_in[1];       // (B,N) i32
    float* out      = (float*)d_out;
    float* out_seg  = out;                       // (B*K, C)
    float* out_pf   = out + (size_t)B_ * K_ * C_; // (B*N, C)

    const size_t smem_bytes = (size_t)TAB_ELEMS * 4 + (size_t)TC * TSTRIDE * 4 + (size_t)TN * 4;
    cudaFuncSetAttribute(seg_phase1, cudaFuncAttributeMaxDynamicSharedMemorySize,
                         (int)smem_bytes);

    dim3 grid(SPLITS, B_);
    seg_phase1<<<grid, TPB, smem_bytes>>>(pf, cid, out_pf);

    const int v_total = B_ * (TAB_ELEMS / 4);    // 65536
    seg_phase2<<<v_total / 256, 256>>>(out_seg);
}